// round 16
// baseline (speedup 1.0000x reference)
#include <cuda_runtime.h>
#include <cuda_bf16.h>
#include <cuda_fp16.h>
#include <cstdint>

#define S_LEN 2048
#define HDIM 512
#define NHEADS 8
#define DHEAD 64
#define BATCH 4
#define ROWS (BATCH * S_LEN)   // 8192
#define QKVLD 1536
#define NSPLIT 2
#define KV_TILES_PER_SPLIT (S_LEN / 64 / NSPLIT)   // 16
#define LOG2E 1.4426950408889634f

// ---------------- scratch ----------------
__device__ float g_scratch_f[2u * ROWS * HDIM];   // h, t
__device__ __nv_bfloat16 g_scratch_b[5u * ROWS * HDIM + 4u * HDIM * HDIM];
__device__ uint32_t g_opart[(size_t)NSPLIT * ROWS * HDIM / 2];  // f16x2 partial O
__device__ float g_lpart[(size_t)NSPLIT * ROWS * NHEADS];       // fp32 partial l

// ======================= helpers =======================
__device__ __forceinline__ uint32_t smem_u32(const void* p) {
    uint32_t a;
    asm("{ .reg .u64 t; cvta.to.shared.u64 t, %1; cvt.u32.u64 %0, t; }" : "=r"(a) : "l"(p));
    return a;
}
__device__ __forceinline__ void ldsm4(uint32_t& r0, uint32_t& r1, uint32_t& r2, uint32_t& r3, uint32_t a) {
    asm volatile("ldmatrix.sync.aligned.m8n8.x4.shared.b16 {%0,%1,%2,%3}, [%4];"
                 : "=r"(r0), "=r"(r1), "=r"(r2), "=r"(r3) : "r"(a));
}
__device__ __forceinline__ void ldsm4t(uint32_t& r0, uint32_t& r1, uint32_t& r2, uint32_t& r3, uint32_t a) {
    asm volatile("ldmatrix.sync.aligned.m8n8.x4.trans.shared.b16 {%0,%1,%2,%3}, [%4];"
                 : "=r"(r0), "=r"(r1), "=r"(r2), "=r"(r3) : "r"(a));
}
__device__ __forceinline__ void mma_bf16(float* c, uint32_t a0, uint32_t a1, uint32_t a2, uint32_t a3,
                                         uint32_t b0, uint32_t b1) {
    asm volatile("mma.sync.aligned.m16n8k16.row.col.f32.bf16.bf16.f32 "
                 "{%0,%1,%2,%3},{%4,%5,%6,%7},{%8,%9},{%0,%1,%2,%3};"
                 : "+f"(c[0]), "+f"(c[1]), "+f"(c[2]), "+f"(c[3])
                 : "r"(a0), "r"(a1), "r"(a2), "r"(a3), "r"(b0), "r"(b1));
}
__device__ __forceinline__ void mma_f16h(uint32_t* d, uint32_t a0, uint32_t a1, uint32_t a2, uint32_t a3,
                                         uint32_t b0, uint32_t b1) {
    asm volatile("mma.sync.aligned.m16n8k16.row.col.f16.f16.f16.f16 "
                 "{%0,%1},{%2,%3,%4,%5},{%6,%7},{%0,%1};"
                 : "+r"(d[0]), "+r"(d[1])
                 : "r"(a0), "r"(a1), "r"(a2), "r"(a3), "r"(b0), "r"(b1));
}
__device__ __forceinline__ uint32_t ex2h2(uint32_t x) {
    uint32_t y;
    asm("ex2.approx.f16x2 %0, %1;" : "=r"(y) : "r"(x));
    return y;
}
__device__ __forceinline__ uint32_t hfma2(uint32_t a, uint32_t b, uint32_t c) {
    uint32_t d;
    asm("fma.rn.f16x2 %0, %1, %2, %3;" : "=r"(d) : "r"(a), "r"(b), "r"(c));
    return d;
}
__device__ __forceinline__ uint32_t hadd2u(uint32_t a, uint32_t b) {
    uint32_t d;
    asm("add.rn.f16x2 %0, %1, %2;" : "=r"(d) : "r"(a), "r"(b));
    return d;
}
__device__ __forceinline__ uint32_t packbf(float a, float b) {
    __nv_bfloat162 p = __floats2bfloat162_rn(a, b);
    return *reinterpret_cast<uint32_t*>(&p);
}
__device__ __forceinline__ uint32_t packh(float a, float b) {
    __half2 h = __floats2half2_rn(a, b);
    return *reinterpret_cast<uint32_t*>(&h);
}
#define CP16(dst, src) asm volatile("cp.async.cg.shared.global [%0], [%1], 16;" :: "r"(dst), "l"(src))
#define CP_COMMIT()    asm volatile("cp.async.commit_group;" ::: "memory")
#define CP_WAIT0()     asm volatile("cp.async.wait_group 0;" ::: "memory")
#define CP_WAIT1()     asm volatile("cp.async.wait_group 1;" ::: "memory")

// ---------------- fused LN1 + weight-conversion ----------------
__global__ __launch_bounds__(128) void ln_conv_kernel(const float* __restrict__ x,
                                                      const float* __restrict__ gamma,
                                                      const float* __restrict__ beta,
                                                      float* __restrict__ out,
                                                      __nv_bfloat16* __restrict__ out_b,
                                                      const float* __restrict__ w0,
                                                      const float* __restrict__ w1,
                                                      const float* __restrict__ w2,
                                                      const float* __restrict__ w3,
                                                      __nv_bfloat16* __restrict__ wout) {
    int t = threadIdx.x;
    if (blockIdx.x >= ROWS) {
        int idx = (blockIdx.x - ROWS) * 128 + t;
        int which = idx >> 16;
        int loc = idx & 65535;
        const float* w = (which == 0) ? w0 : (which == 1) ? w1 : (which == 2) ? w2 : w3;
        float4 v = reinterpret_cast<const float4*>(w)[loc];
        uint2 u;
        u.x = packbf(v.x, v.y);
        u.y = packbf(v.z, v.w);
        reinterpret_cast<uint2*>(wout + (size_t)which * HDIM * HDIM)[loc] = u;
        return;
    }
    int row = blockIdx.x;
    const float4* xr = reinterpret_cast<const float4*>(x + (size_t)row * HDIM);
    float4 v = xr[t];
    float s  = v.x + v.y + v.z + v.w;
    float sq = v.x * v.x + v.y * v.y + v.z * v.z + v.w * v.w;
    #pragma unroll
    for (int o = 16; o > 0; o >>= 1) {
        s  += __shfl_xor_sync(0xffffffffu, s,  o);
        sq += __shfl_xor_sync(0xffffffffu, sq, o);
    }
    __shared__ float ss[4], ssq[4];
    if ((t & 31) == 0) { ss[t >> 5] = s; ssq[t >> 5] = sq; }
    __syncthreads();
    s  = ss[0] + ss[1] + ss[2] + ss[3];
    sq = ssq[0] + ssq[1] + ssq[2] + ssq[3];
    float mu   = s * (1.0f / HDIM);
    float var  = sq * (1.0f / HDIM) - mu * mu;
    float rstd = rsqrtf(var + 1e-12f);
    float4 gg = reinterpret_cast<const float4*>(gamma)[t];
    float4 bb = reinterpret_cast<const float4*>(beta)[t];
    float4 o;
    o.x = (v.x - mu) * rstd * gg.x + bb.x;
    o.y = (v.y - mu) * rstd * gg.y + bb.y;
    o.z = (v.z - mu) * rstd * gg.z + bb.z;
    o.w = (v.w - mu) * rstd * gg.w + bb.w;
    reinterpret_cast<float4*>(out + (size_t)row * HDIM)[t] = o;
    uint2 u;
    u.x = packbf(o.x, o.y);
    u.y = packbf(o.z, o.w);
    reinterpret_cast<uint2*>(out_b + (size_t)row * HDIM)[t] = u;
}

// ---------------- plain LayerNorm (LN2) ----------------
__global__ __launch_bounds__(128) void ln_kernel(const float* __restrict__ x,
                                                 const float* __restrict__ gamma,
                                                 const float* __restrict__ beta,
                                                 float* __restrict__ out) {
    int row = blockIdx.x;
    int t = threadIdx.x;
    const float4* xr = reinterpret_cast<const float4*>(x + (size_t)row * HDIM);
    float4 v = xr[t];
    float s  = v.x + v.y + v.z + v.w;
    float sq = v.x * v.x + v.y * v.y + v.z * v.z + v.w * v.w;
    #pragma unroll
    for (int o = 16; o > 0; o >>= 1) {
        s  += __shfl_xor_sync(0xffffffffu, s,  o);
        sq += __shfl_xor_sync(0xffffffffu, sq, o);
    }
    __shared__ float ss[4], ssq[4];
    if ((t & 31) == 0) { ss[t >> 5] = s; ssq[t >> 5] = sq; }
    __syncthreads();
    s  = ss[0] + ss[1] + ss[2] + ss[3];
    sq = ssq[0] + ssq[1] + ssq[2] + ssq[3];
    float mu   = s * (1.0f / HDIM);
    float var  = sq * (1.0f / HDIM) - mu * mu;
    float rstd = rsqrtf(var + 1e-12f);
    float4 gg = reinterpret_cast<const float4*>(gamma)[t];
    float4 bb = reinterpret_cast<const float4*>(beta)[t];
    float4 o;
    o.x = (v.x - mu) * rstd * gg.x + bb.x;
    o.y = (v.y - mu) * rstd * gg.y + bb.y;
    o.z = (v.z - mu) * rstd * gg.z + bb.z;
    o.w = (v.w - mu) * rstd * gg.w + bb.w;
    reinterpret_cast<float4*>(out + (size_t)row * HDIM)[t] = o;
}

// ---------------- QKV GEMM: 128x128 tile, 3-stage cp.async (K-stage 32) ----------------
#define G2_SMEM 61440
__global__ __launch_bounds__(256, 2) void gemm_qkv_kernel(const __nv_bfloat16* __restrict__ A,
                                                          const __nv_bfloat16* __restrict__ W,
                                                          const float* __restrict__ bq,
                                                          const float* __restrict__ bk,
                                                          const float* __restrict__ bv,
                                                          __nv_bfloat16* __restrict__ C) {
    extern __shared__ __align__(16) char gsm[];
    int t = threadIdx.x, wid = t >> 5, lane = t & 31;
    int wm = wid >> 2, wn = wid & 3;
    int m0 = blockIdx.y * 128, n0 = blockIdx.x * 128;
    uint32_t sb = smem_u32(gsm);

    #define G2_ISSUE(k0, s) do { \
        uint32_t _ab = sb + (s) * 10240, _bb = sb + 30720 + (s) * 10240; \
        _Pragma("unroll") \
        for (int e = 0; e < 2; e++) { \
            int idx = t + e * 256; int r = idx >> 2; int c = (idx & 3) * 8; \
            CP16(_ab + (uint32_t)(r * 40 + c) * 2, A + (size_t)(m0 + r) * HDIM + (k0) + c); \
            CP16(_bb + (uint32_t)(r * 40 + c) * 2, W + (size_t)(n0 + r) * HDIM + (k0) + c); \
        } \
        CP_COMMIT(); \
    } while (0)

    G2_ISSUE(0, 0);
    G2_ISSUE(32, 1);

    float c[4][4][4] = {};

    for (int k = 0; k < 16; k++) {
        if (k == 15) CP_WAIT0(); else CP_WAIT1();
        __syncthreads();
        if (k + 2 < 16) G2_ISSUE((k + 2) * 32, (k + 2) % 3);

        uint32_t ab = sb + (k % 3) * 10240;
        uint32_t bb = sb + 30720 + (k % 3) * 10240;

        uint32_t bg[4][4];
        #pragma unroll
        for (int g = 0; g < 4; g++) {
            int r = wn * 32 + g * 8 + (lane & 7);
            int cb = (lane >> 3) << 3;
            ldsm4(bg[g][0], bg[g][1], bg[g][2], bg[g][3], bb + (uint32_t)(r * 40 + cb) * 2);
        }
        #pragma unroll
        for (int kk = 0; kk < 2; kk++) {
            uint32_t aa[4][4];
            #pragma unroll
            for (int mf = 0; mf < 4; mf++) {
                int r = wm * 64 + mf * 16 + (lane & 15);
                int cb = kk * 16 + ((lane >> 4) << 3);
                ldsm4(aa[mf][0], aa[mf][1], aa[mf][2], aa[mf][3], ab + (uint32_t)(r * 40 + cb) * 2);
            }
            #pragma unroll
            for (int mf = 0; mf < 4; mf++)
                #pragma unroll
                for (int g = 0; g < 4; g++)
                    mma_bf16(c[mf][g], aa[mf][0], aa[mf][1], aa[mf][2], aa[mf][3],
                             bg[g][kk * 2], bg[g][kk * 2 + 1]);
        }
    }

    int which = n0 >> 9;
    const float* bias = (which == 0) ? bq : (which == 1) ? bk : bv;
    int nloc = n0 & 511;
    #pragma unroll
    for (int mf = 0; mf < 4; mf++) {
        int r0 = m0 + wm * 64 + mf * 16 + (lane >> 2);
        #pragma unroll
        for (int g = 0; g < 4; g++) {
            int cl = nloc + wn * 32 + g * 8 + 2 * (lane & 3);
            float b0v = bias[cl], b1v = bias[cl + 1];
            int col = n0 + wn * 32 + g * 8 + 2 * (lane & 3);
            *reinterpret_cast<uint32_t*>(C + (size_t)r0 * QKVLD + col) =
                packh(c[mf][g][0] + b0v, c[mf][g][1] + b1v);
            *reinterpret_cast<uint32_t*>(C + (size_t)(r0 + 8) * QKVLD + col) =
                packh(c[mf][g][2] + b0v, c[mf][g][3] + b1v);
        }
    }
}

// ---------------- wo GEMM with fused split-combine in A-staging ----------------
// A[m,k] = (Opart0[m,k] + Opart1[m,k]) / (l0[m,h]+l1[m,h]) computed during staging.
__global__ __launch_bounds__(256, 2) void gemm_wo_kernel(const uint32_t* __restrict__ Opart,
                                                         const float* __restrict__ Lpart,
                                                         const __nv_bfloat16* __restrict__ W,
                                                         const float* __restrict__ bo,
                                                         const float* __restrict__ res,
                                                         float* __restrict__ Cout) {
    extern __shared__ __align__(16) char gsm[];
    int t = threadIdx.x, wid = t >> 5, lane = t & 31;
    int wm = wid >> 2, wn = wid & 3;
    int m0 = blockIdx.y * 128, n0 = blockIdx.x * 128;
    uint32_t sb = smem_u32(gsm);

    #define GW_ISSUE_B(k0, s) do { \
        uint32_t _bb = sb + 30720 + (s) * 10240; \
        _Pragma("unroll") \
        for (int e = 0; e < 2; e++) { \
            int idx = t + e * 256; int r = idx >> 2; int c = (idx & 3) * 8; \
            CP16(_bb + (uint32_t)(r * 40 + c) * 2, W + (size_t)(n0 + r) * HDIM + (k0) + c); \
        } \
        CP_COMMIT(); \
    } while (0)

    uint4 au0[2], au1[2];
    float ala[2], alb[2];

    #define GW_LDG_A(k0) do { \
        int head = (k0) >> 6; \
        _Pragma("unroll") \
        for (int e = 0; e < 2; e++) { \
            int idx = t + e * 256; int r = idx >> 2; int c = (idx & 3) * 8; \
            int row = m0 + r; \
            au0[e] = *reinterpret_cast<const uint4*>(Opart + (size_t)row * (HDIM / 2) + ((k0) + c) / 2); \
            au1[e] = *reinterpret_cast<const uint4*>(Opart + (size_t)(ROWS + row) * (HDIM / 2) + ((k0) + c) / 2); \
            ala[e] = Lpart[(size_t)row * NHEADS + head]; \
            alb[e] = Lpart[(size_t)(ROWS + row) * NHEADS + head]; \
        } \
    } while (0)

    #define GW_STS_A(s) do { \
        uint32_t _ab = sb + (s) * 10240; \
        _Pragma("unroll") \
        for (int e = 0; e < 2; e++) { \
            int idx = t + e * 256; int r = idx >> 2; int c = (idx & 3) * 8; \
            float inv = 1.0f / (ala[e] + alb[e]); \
            const uint32_t* a0p = reinterpret_cast<const uint32_t*>(&au0[e]); \
            const uint32_t* a1p = reinterpret_cast<const uint32_t*>(&au1[e]); \
            uint4 ov; uint32_t* ovp = reinterpret_cast<uint32_t*>(&ov); \
            _Pragma("unroll") \
            for (int i = 0; i < 4; i++) { \
                float2 f0 = __half22float2(*reinterpret_cast<const __half2*>(&a0p[i])); \
                float2 f1 = __half22float2(*reinterpret_cast<const __half2*>(&a1p[i])); \
                ovp[i] = packbf((f0.x + f1.x) * inv, (f0.y + f1.y) * inv); \
            } \
            *reinterpret_cast<uint4*>(gsm + (_ab - sb) + (uint32_t)(r * 40 + c) * 2) = ov; \
        } \
    } while (0)

    // prologue
    GW_ISSUE_B(0, 0);
    GW_ISSUE_B(32, 1);
    GW_LDG_A(0);
    GW_STS_A(0);
    GW_LDG_A(32);
    GW_STS_A(1);

    float c[4][4][4] = {};

    for (int k = 0; k < 16; k++) {
        if (k == 15) CP_WAIT0(); else CP_WAIT1();
        __syncthreads();
        if (k + 2 < 16) {
            GW_ISSUE_B((k + 2) * 32, (k + 2) % 3);
            GW_LDG_A((k + 2) * 32);
        }

        uint32_t ab = sb + (k % 3) * 10240;
        uint32_t bb = sb + 30720 + (k % 3) * 10240;

        uint32_t bg[4][4];
        #pragma unroll
        for (int g = 0; g < 4; g++) {
            int r = wn * 32 + g * 8 + (lane & 7);
            int cb = (lane >> 3) << 3;
            ldsm4(bg[g][0], bg[g][1], bg[g][2], bg[g][3], bb + (uint32_t)(r * 40 + cb) * 2);
        }
        #pragma unroll
        for (int kk = 0; kk < 2; kk++) {
            uint32_t aa[4][4];
            #pragma unroll
            for (int mf = 0; mf < 4; mf++) {
                int r = wm * 64 + mf * 16 + (lane & 15);
                int cb = kk * 16 + ((lane >> 4) << 3);
                ldsm4(aa[mf][0], aa[mf][1], aa[mf][2], aa[mf][3], ab + (uint32_t)(r * 40 + cb) * 2);
            }
            #pragma unroll
            for (int mf = 0; mf < 4; mf++)
                #pragma unroll
                for (int g = 0; g < 4; g++)
                    mma_bf16(c[mf][g], aa[mf][0], aa[mf][1], aa[mf][2], aa[mf][3],
                             bg[g][kk * 2], bg[g][kk * 2 + 1]);
        }

        if (k + 2 < 16) GW_STS_A((k + 2) % 3);
    }

    #pragma unroll
    for (int mf = 0; mf < 4; mf++) {
        int r0 = m0 + wm * 64 + mf * 16 + (lane >> 2);
        #pragma unroll
        for (int g = 0; g < 4; g++) {
            int cl = n0 + wn * 32 + g * 8 + 2 * (lane & 3);
            float b0v = bo[cl], b1v = bo[cl + 1];
            size_t off0 = (size_t)r0 * HDIM + cl;
            size_t off1 = (size_t)(r0 + 8) * HDIM + cl;
            float2 ra = *reinterpret_cast<const float2*>(&res[off0]);
            float2 rb = *reinterpret_cast<const float2*>(&res[off1]);
            *reinterpret_cast<float2*>(Cout + off0) =
                make_float2(c[mf][g][0] + b0v + ra.x, c[mf][g][1] + b1v + ra.y);
            *reinterpret_cast<float2*>(Cout + off1) =
                make_float2(c[mf][g][2] + b0v + rb.x, c[mf][g][3] + b1v + rb.y);
        }
    }
}

// ---------------- attention: split-KV NSPLIT=2, l on fma pipe ----------------
#define A_QS 0
#define A_KS 16384
#define A_VS 32768
#define A_MK 49152
#define ATT_SMEM 51200

__global__ __launch_bounds__(128, 4) void att_mma_kernel(const __nv_bfloat16* __restrict__ QKV,
                                                         const float* __restrict__ mask,
                                                         uint32_t* __restrict__ Opart,
                                                         float* __restrict__ Lpart) {
    extern __shared__ __align__(16) char asm_[];
    uint32_t sb = smem_u32(asm_);
    uint32_t* mskh2 = reinterpret_cast<uint32_t*>(asm_ + A_MK);

    int t = threadIdx.x, wid = t >> 5, lane = t & 31;
    int q0 = blockIdx.x * 128;
    int b = blockIdx.y >> 3, h = blockIdx.y & 7;
    int split = blockIdx.z;
    int kt0 = split * KV_TILES_PER_SPLIT;
    int ktend = kt0 + KV_TILES_PER_SPLIT;

    const __nv_bfloat16* qg = QKV + (size_t)b * S_LEN * QKVLD + h * DHEAD;
    const __nv_bfloat16* kg = QKV + (size_t)b * S_LEN * QKVLD + 512 + h * DHEAD;
    const __nv_bfloat16* vg = QKV + (size_t)b * S_LEN * QKVLD + 1024 + h * DHEAD;

    #pragma unroll
    for (int e = 0; e < 8; e++) {
        int idx = t + e * 128;
        int r = idx >> 3, c8 = idx & 7;
        CP16(sb + A_QS + (uint32_t)(r * 128 + ((c8 ^ (r & 7)) << 4)),
             qg + (size_t)(q0 + r) * QKVLD + c8 * 8);
    }
    #pragma unroll
    for (int e = 0; e < 4; e++) {
        int idx = t + e * 128;
        int r = idx >> 3, c8 = idx & 7;
        uint32_t off = (uint32_t)(r * 128 + ((c8 ^ (r & 7)) << 4));
        CP16(sb + A_KS + off, kg + (size_t)(kt0 * 64 + r) * QKVLD + c8 * 8);
        CP16(sb + A_VS + off, vg + (size_t)(kt0 * 64 + r) * QKVLD + c8 * 8);
    }
    CP_COMMIT();
    #pragma unroll
    for (int e = 0; e < 4; e++) {
        int i = t + e * 128;
        float2 mv = reinterpret_cast<const float2*>(mask + (size_t)b * S_LEN)[split * 512 + i];
        mskh2[i] = packh(mv.x * LOG2E, mv.y * LOG2E);
    }
    CP_WAIT0();
    __syncthreads();

    uint32_t qa[2][4][4];
    #pragma unroll
    for (int mf = 0; mf < 2; mf++) {
        int r = wid * 32 + mf * 16 + (lane & 15);
        #pragma unroll
        for (int kk = 0; kk < 4; kk++) {
            int chunk = kk * 2 + (lane >> 4);
            ldsm4(qa[mf][kk][0], qa[mf][kk][1], qa[mf][kk][2], qa[mf][kk][3],
                  sb + A_QS + (uint32_t)(r * 128 + ((chunk ^ (lane & 7)) << 4)));
        }
    }

    uint32_t o[2][8][2] = {};
    float lacc[2][2] = {};
    const uint32_t sc2 = packh(0.125f * LOG2E, 0.125f * LOG2E);

    for (int kt = kt0; kt < ktend; kt++) {
        if (kt + 1 < ktend) {
            int kb1 = (kt + 1) * 64;
            uint32_t s1off = (uint32_t)((kt + 1) & 1) * 8192;
            #pragma unroll
            for (int e = 0; e < 4; e++) {
                int idx = t + e * 128;
                int r = idx >> 3, c8 = idx & 7;
                uint32_t off = s1off + (uint32_t)(r * 128 + ((c8 ^ (r & 7)) << 4));
                CP16(sb + A_KS + off, kg + (size_t)(kb1 + r) * QKVLD + c8 * 8);
                CP16(sb + A_VS + off, vg + (size_t)(kb1 + r) * QKVLD + c8 * 8);
            }
            CP_COMMIT();
        }

        uint32_t ks_b = sb + A_KS + (uint32_t)(kt & 1) * 8192;
        uint32_t vs_b = sb + A_VS + (uint32_t)(kt & 1) * 8192;
        int kbl = (kt - kt0) * 64;

        uint32_t s[2][8][2] = {};
        #pragma unroll
        for (int nn = 0; nn < 8; nn++) {
            int r = nn * 8 + (lane & 7);
            int c0 = ((lane >> 3) ^ (lane & 7)) << 4;
            int c1 = ((4 + (lane >> 3)) ^ (lane & 7)) << 4;
            uint32_t b0, b1, b2, b3, b4, b5, b6, b7;
            ldsm4(b0, b1, b2, b3, ks_b + (uint32_t)(r * 128 + c0));
            ldsm4(b4, b5, b6, b7, ks_b + (uint32_t)(r * 128 + c1));
            #pragma unroll
            for (int mf = 0; mf < 2; mf++) {
                mma_f16h(s[mf][nn], qa[mf][0][0], qa[mf][0][1], qa[mf][0][2], qa[mf][0][3], b0, b1);
                mma_f16h(s[mf][nn], qa[mf][1][0], qa[mf][1][1], qa[mf][1][2], qa[mf][1][3], b2, b3);
                mma_f16h(s[mf][nn], qa[mf][2][0], qa[mf][2][1], qa[mf][2][2], qa[mf][2][3], b4, b5);
                mma_f16h(s[mf][nn], qa[mf][3][0], qa[mf][3][1], qa[mf][3][2], qa[mf][3][3], b6, b7);
            }
        }

        #pragma unroll
        for (int mf = 0; mf < 2; mf++) {
            uint32_t lh0 = 0u, lh1 = 0u;
            #pragma unroll
            for (int nn = 0; nn < 8; nn++) {
                uint32_t mk = mskh2[(kbl >> 1) + nn * 4 + (lane & 3)];
                s[mf][nn][0] = ex2h2(hfma2(s[mf][nn][0], sc2, mk));
                s[mf][nn][1] = ex2h2(hfma2(s[mf][nn][1], sc2, mk));
                lh0 = hadd2u(lh0, s[mf][nn][0]);
                lh1 = hadd2u(lh1, s[mf][nn][1]);
            }
            float2 f0 = __half22float2(*reinterpret_cast<__half2*>(&lh0));
            float2 f1 = __half22float2(*reinterpret_cast<__half2*>(&lh1));
            lacc[mf][0] += f0.x + f0.y;
            lacc[mf][1] += f1.x + f1.y;
        }

        #pragma unroll
        for (int nn = 0; nn < 8; nn++) {
            uint32_t v0, v1, v2, v3, u0, u1, u2, u3;
            int ch = (nn ^ (lane & 7)) << 4;
            ldsm4t(v0, v1, v2, v3, vs_b + (uint32_t)(lane * 128 + ch));
            ldsm4t(u0, u1, u2, u3, vs_b + (uint32_t)((32 + lane) * 128 + ch));
            #pragma unroll
            for (int mf = 0; mf < 2; mf++) {
                mma_f16h(o[mf][nn], s[mf][0][0], s[mf][0][1], s[mf][1][0], s[mf][1][1], v0, v1);
                mma_f16h(o[mf][nn], s[mf][2][0], s[mf][2][1], s[mf][3][0], s[mf][3][1], v2, v3);
                mma_f16h(o[mf][nn], s[mf][4][0], s[mf][4][1], s[mf][5][0], s[mf][5][1], u0, u1);
                mma_f16h(o[mf][nn], s[mf][6][0], s[mf][6][1], s[mf][7][0], s[mf][7][1], u2, u3);
            }
        }

        if (kt + 1 < ktend) {
            CP_WAIT0();
            __syncthreads();
        }
    }

    #pragma unroll
    for (int mf = 0; mf < 2; mf++)
        #pragma unroll
        for (int i = 0; i < 2; i++) {
            lacc[mf][i] += __shfl_xor_sync(0xffffffffu, lacc[mf][i], 1);
            lacc[mf][i] += __shfl_xor_sync(0xffffffffu, lacc[mf][i], 2);
        }

    int rbase = b * S_LEN + q0 + wid * 32 + (lane >> 2);
    uint32_t* op = Opart + (size_t)split * ROWS * (HDIM / 2);
    #pragma unroll
    for (int nn = 0; nn < 8; nn++) {
        int colh = (h * DHEAD + nn * 8 + 2 * (lane & 3)) >> 1;
        #pragma unroll
        for (int mf = 0; mf < 2; mf++) {
            op[(size_t)(rbase + mf * 16) * (HDIM / 2) + colh] = o[mf][nn][0];
            op[(size_t)(rbase + mf * 16 + 8) * (HDIM / 2) + colh] = o[mf][nn][1];
        }
    }
    if ((lane & 3) == 0) {
        float* lp = Lpart + (size_t)split * ROWS * NHEADS;
        #pragma unroll
        for (int mf = 0; mf < 2; mf++) {
            lp[(size_t)(rbase + mf * 16) * NHEADS + h] = lacc[mf][0];
            lp[(size_t)(rbase + mf * 16 + 8) * NHEADS + h] = lacc[mf][1];
        }
    }
}

// ---------------- launcher ----------------
extern "C" void kernel_launch(void* const* d_in, const int* in_sizes, int n_in,
                              void* d_out, int out_size) {
    const float* hidden = (const float*)d_in[0];
    const float* amask  = (const float*)d_in[1];
    const float* ln1_g  = (const float*)d_in[2];
    const float* ln1_b  = (const float*)d_in[3];
    const float* wq     = (const float*)d_in[4];
    const float* bq     = (const float*)d_in[5];
    const float* wk     = (const float*)d_in[6];
    const float* bk     = (const float*)d_in[7];
    const float* wv     = (const float*)d_in[8];
    const float* bv     = (const float*)d_in[9];
    const float* wo     = (const float*)d_in[10];
    const float* bo     = (const float*)d_in[11];
    const float* ln2_g  = (const float*)d_in[12];
    const float* ln2_b  = (const float*)d_in[13];
    float* out = (float*)d_out;

    float* scrf = nullptr;
    __nv_bfloat16* scrb = nullptr;
    uint32_t* opart = nullptr;
    float* lpart = nullptr;
    cudaGetSymbolAddress((void**)&scrf, g_scratch_f);
    cudaGetSymbolAddress((void**)&scrb, g_scratch_b);
    cudaGetSymbolAddress((void**)&opart, g_opart);
    cudaGetSymbolAddress((void**)&lpart, g_lpart);
    const size_t SZ = (size_t)ROWS * HDIM;
    const size_t WSZ = (size_t)HDIM * HDIM;
    float* g_h = scrf;
    float* g_t = scrf + SZ;
    __nv_bfloat16* g_hb   = scrb;
    __nv_bfloat16* g_qkv  = scrb + SZ;          // [ROWS][1536], fp16 bits
    __nv_bfloat16* g_wb   = scrb + 5 * SZ;      // wq|wk|wv|wo

    static bool attr_done = false;
    if (!attr_done) {
        cudaFuncSetAttribute(gemm_qkv_kernel, cudaFuncAttributeMaxDynamicSharedMemorySize, G2_SMEM);
        cudaFuncSetAttribute(gemm_wo_kernel,  cudaFuncAttributeMaxDynamicSharedMemorySize, G2_SMEM);
        cudaFuncSetAttribute(att_mma_kernel,  cudaFuncAttributeMaxDynamicSharedMemorySize, ATT_SMEM);
        attr_done = true;
    }

    // 1) fused LN1 + weight conversion
    ln_conv_kernel<<<ROWS + 2048, 128>>>(hidden, ln1_g, ln1_b, g_h, g_hb,
                                         wq, wk, wv, wo, g_wb);
    // 2) fused QKV projection (fp16 outputs)
    dim3 qkv_grid(3 * HDIM / 128, ROWS / 128);
    gemm_qkv_kernel<<<qkv_grid, 256, G2_SMEM>>>(g_hb, g_wb, bq, bk, bv, g_qkv);
    // 3) attention partials (split-KV, NSPLIT=2)
    dim3 att_grid(S_LEN / 128, BATCH * NHEADS, NSPLIT);   // (16, 32, 2) = 1024 CTAs
    att_mma_kernel<<<att_grid, 128, ATT_SMEM>>>(g_qkv, amask, opart, lpart);
    // 4) output projection with fused combine + bias + residual
    dim3 wo_grid(HDIM / 128, ROWS / 128);
    gemm_wo_kernel<<<wo_grid, 256, G2_SMEM>>>(opart, lpart, g_wb + 3 * WSZ, bo, g_h, g_t);
    // 5) LN2
    ln_kernel<<<ROWS, 128>>>(g_t, ln2_g, ln2_b, out);
}

// round 17
// speedup vs baseline: 1.1154x; 1.1154x over previous
#include <cuda_runtime.h>
#include <cuda_bf16.h>
#include <cuda_fp16.h>
#include <cstdint>

#define S_LEN 2048
#define HDIM 512
#define NHEADS 8
#define DHEAD 64
#define BATCH 4
#define ROWS (BATCH * S_LEN)   // 8192
#define HALF_ROWS (ROWS / 2)
#define QKVLD 1536
#define NSPLIT 2
#define KV_TILES_PER_SPLIT (S_LEN / 64 / NSPLIT)   // 16
#define LOG2E 1.4426950408889634f

// ---------------- scratch ----------------
__device__ float g_scratch_f[2u * ROWS * HDIM];   // h, t
__device__ __nv_bfloat16 g_scratch_b[5u * ROWS * HDIM + 4u * HDIM * HDIM];
__device__ uint32_t g_opart[(size_t)NSPLIT * ROWS * HDIM / 2];  // f16x2 partial O
__device__ float g_lpart[(size_t)NSPLIT * ROWS * NHEADS];       // fp32 partial l

// ======================= helpers =======================
__device__ __forceinline__ uint32_t smem_u32(const void* p) {
    uint32_t a;
    asm("{ .reg .u64 t; cvta.to.shared.u64 t, %1; cvt.u32.u64 %0, t; }" : "=r"(a) : "l"(p));
    return a;
}
__device__ __forceinline__ void ldsm4(uint32_t& r0, uint32_t& r1, uint32_t& r2, uint32_t& r3, uint32_t a) {
    asm volatile("ldmatrix.sync.aligned.m8n8.x4.shared.b16 {%0,%1,%2,%3}, [%4];"
                 : "=r"(r0), "=r"(r1), "=r"(r2), "=r"(r3) : "r"(a));
}
__device__ __forceinline__ void ldsm4t(uint32_t& r0, uint32_t& r1, uint32_t& r2, uint32_t& r3, uint32_t a) {
    asm volatile("ldmatrix.sync.aligned.m8n8.x4.trans.shared.b16 {%0,%1,%2,%3}, [%4];"
                 : "=r"(r0), "=r"(r1), "=r"(r2), "=r"(r3) : "r"(a));
}
__device__ __forceinline__ void mma_bf16(float* c, uint32_t a0, uint32_t a1, uint32_t a2, uint32_t a3,
                                         uint32_t b0, uint32_t b1) {
    asm volatile("mma.sync.aligned.m16n8k16.row.col.f32.bf16.bf16.f32 "
                 "{%0,%1,%2,%3},{%4,%5,%6,%7},{%8,%9},{%0,%1,%2,%3};"
                 : "+f"(c[0]), "+f"(c[1]), "+f"(c[2]), "+f"(c[3])
                 : "r"(a0), "r"(a1), "r"(a2), "r"(a3), "r"(b0), "r"(b1));
}
__device__ __forceinline__ void mma_f16h(uint32_t* d, uint32_t a0, uint32_t a1, uint32_t a2, uint32_t a3,
                                         uint32_t b0, uint32_t b1) {
    asm volatile("mma.sync.aligned.m16n8k16.row.col.f16.f16.f16.f16 "
                 "{%0,%1},{%2,%3,%4,%5},{%6,%7},{%0,%1};"
                 : "+r"(d[0]), "+r"(d[1])
                 : "r"(a0), "r"(a1), "r"(a2), "r"(a3), "r"(b0), "r"(b1));
}
__device__ __forceinline__ uint32_t ex2h2(uint32_t x) {
    uint32_t y;
    asm("ex2.approx.f16x2 %0, %1;" : "=r"(y) : "r"(x));
    return y;
}
__device__ __forceinline__ uint32_t hfma2(uint32_t a, uint32_t b, uint32_t c) {
    uint32_t d;
    asm("fma.rn.f16x2 %0, %1, %2, %3;" : "=r"(d) : "r"(a), "r"(b), "r"(c));
    return d;
}
__device__ __forceinline__ uint32_t hadd2u(uint32_t a, uint32_t b) {
    uint32_t d;
    asm("add.rn.f16x2 %0, %1, %2;" : "=r"(d) : "r"(a), "r"(b));
    return d;
}
__device__ __forceinline__ uint32_t packbf(float a, float b) {
    __nv_bfloat162 p = __floats2bfloat162_rn(a, b);
    return *reinterpret_cast<uint32_t*>(&p);
}
__device__ __forceinline__ uint32_t packh(float a, float b) {
    __half2 h = __floats2half2_rn(a, b);
    return *reinterpret_cast<uint32_t*>(&h);
}
#define CP16(dst, src) asm volatile("cp.async.cg.shared.global [%0], [%1], 16;" :: "r"(dst), "l"(src))
#define CP_COMMIT()    asm volatile("cp.async.commit_group;" ::: "memory")
#define CP_WAIT0()     asm volatile("cp.async.wait_group 0;" ::: "memory")
#define CP_WAIT1()     asm volatile("cp.async.wait_group 1;" ::: "memory")

// ---------------- fused LN1 + weight-conversion ----------------
__global__ __launch_bounds__(128) void ln_conv_kernel(const float* __restrict__ x,
                                                      const float* __restrict__ gamma,
                                                      const float* __restrict__ beta,
                                                      float* __restrict__ out,
                                                      __nv_bfloat16* __restrict__ out_b,
                                                      const float* __restrict__ w0,
                                                      const float* __restrict__ w1,
                                                      const float* __restrict__ w2,
                                                      const float* __restrict__ w3,
                                                      __nv_bfloat16* __restrict__ wout) {
    int t = threadIdx.x;
    if (blockIdx.x >= ROWS) {
        int idx = (blockIdx.x - ROWS) * 128 + t;
        int which = idx >> 16;
        int loc = idx & 65535;
        const float* w = (which == 0) ? w0 : (which == 1) ? w1 : (which == 2) ? w2 : w3;
        float4 v = reinterpret_cast<const float4*>(w)[loc];
        uint2 u;
        u.x = packbf(v.x, v.y);
        u.y = packbf(v.z, v.w);
        reinterpret_cast<uint2*>(wout + (size_t)which * HDIM * HDIM)[loc] = u;
        return;
    }
    int row = blockIdx.x;
    const float4* xr = reinterpret_cast<const float4*>(x + (size_t)row * HDIM);
    float4 v = xr[t];
    float s  = v.x + v.y + v.z + v.w;
    float sq = v.x * v.x + v.y * v.y + v.z * v.z + v.w * v.w;
    #pragma unroll
    for (int o = 16; o > 0; o >>= 1) {
        s  += __shfl_xor_sync(0xffffffffu, s,  o);
        sq += __shfl_xor_sync(0xffffffffu, sq, o);
    }
    __shared__ float ss[4], ssq[4];
    if ((t & 31) == 0) { ss[t >> 5] = s; ssq[t >> 5] = sq; }
    __syncthreads();
    s  = ss[0] + ss[1] + ss[2] + ss[3];
    sq = ssq[0] + ssq[1] + ssq[2] + ssq[3];
    float mu   = s * (1.0f / HDIM);
    float var  = sq * (1.0f / HDIM) - mu * mu;
    float rstd = rsqrtf(var + 1e-12f);
    float4 gg = reinterpret_cast<const float4*>(gamma)[t];
    float4 bb = reinterpret_cast<const float4*>(beta)[t];
    float4 o;
    o.x = (v.x - mu) * rstd * gg.x + bb.x;
    o.y = (v.y - mu) * rstd * gg.y + bb.y;
    o.z = (v.z - mu) * rstd * gg.z + bb.z;
    o.w = (v.w - mu) * rstd * gg.w + bb.w;
    reinterpret_cast<float4*>(out + (size_t)row * HDIM)[t] = o;
    uint2 u;
    u.x = packbf(o.x, o.y);
    u.y = packbf(o.z, o.w);
    reinterpret_cast<uint2*>(out_b + (size_t)row * HDIM)[t] = u;
}

// ---------------- plain LayerNorm (LN2), row-offset ----------------
__global__ __launch_bounds__(128) void ln_kernel(const float* __restrict__ x,
                                                 const float* __restrict__ gamma,
                                                 const float* __restrict__ beta,
                                                 float* __restrict__ out,
                                                 int row0) {
    int row = row0 + blockIdx.x;
    int t = threadIdx.x;
    const float4* xr = reinterpret_cast<const float4*>(x + (size_t)row * HDIM);
    float4 v = xr[t];
    float s  = v.x + v.y + v.z + v.w;
    float sq = v.x * v.x + v.y * v.y + v.z * v.z + v.w * v.w;
    #pragma unroll
    for (int o = 16; o > 0; o >>= 1) {
        s  += __shfl_xor_sync(0xffffffffu, s,  o);
        sq += __shfl_xor_sync(0xffffffffu, sq, o);
    }
    __shared__ float ss[4], ssq[4];
    if ((t & 31) == 0) { ss[t >> 5] = s; ssq[t >> 5] = sq; }
    __syncthreads();
    s  = ss[0] + ss[1] + ss[2] + ss[3];
    sq = ssq[0] + ssq[1] + ssq[2] + ssq[3];
    float mu   = s * (1.0f / HDIM);
    float var  = sq * (1.0f / HDIM) - mu * mu;
    float rstd = rsqrtf(var + 1e-12f);
    float4 gg = reinterpret_cast<const float4*>(gamma)[t];
    float4 bb = reinterpret_cast<const float4*>(beta)[t];
    float4 o;
    o.x = (v.x - mu) * rstd * gg.x + bb.x;
    o.y = (v.y - mu) * rstd * gg.y + bb.y;
    o.z = (v.z - mu) * rstd * gg.z + bb.z;
    o.w = (v.w - mu) * rstd * gg.w + bb.w;
    reinterpret_cast<float4*>(out + (size_t)row * HDIM)[t] = o;
}

// ---------------- GEMM v2: 128x128 tile, 3-stage cp.async, row-offset ----------------
#define G2_SMEM 61440
template <bool QKV>
__global__ __launch_bounds__(256, 2) void gemm2_kernel(const __nv_bfloat16* __restrict__ A,
                                                       const __nv_bfloat16* __restrict__ W,
                                                       const float* __restrict__ bq,
                                                       const float* __restrict__ bk,
                                                       const float* __restrict__ bv,
                                                       const float* __restrict__ res,
                                                       void* __restrict__ Cout,
                                                       int row0) {
    extern __shared__ __align__(16) char gsm[];
    int t = threadIdx.x, wid = t >> 5, lane = t & 31;
    int wm = wid >> 2, wn = wid & 3;
    int m0 = row0 + blockIdx.y * 128, n0 = blockIdx.x * 128;
    uint32_t sb = smem_u32(gsm);

    #define G2_ISSUE(k0, s) do { \
        uint32_t _ab = sb + (s) * 10240, _bb = sb + 30720 + (s) * 10240; \
        _Pragma("unroll") \
        for (int e = 0; e < 2; e++) { \
            int idx = t + e * 256; int r = idx >> 2; int c = (idx & 3) * 8; \
            CP16(_ab + (uint32_t)(r * 40 + c) * 2, A + (size_t)(m0 + r) * HDIM + (k0) + c); \
            CP16(_bb + (uint32_t)(r * 40 + c) * 2, W + (size_t)(n0 + r) * HDIM + (k0) + c); \
        } \
        CP_COMMIT(); \
    } while (0)

    G2_ISSUE(0, 0);
    G2_ISSUE(32, 1);

    float c[4][4][4] = {};

    for (int k = 0; k < 16; k++) {
        if (k == 15) CP_WAIT0(); else CP_WAIT1();
        __syncthreads();
        if (k + 2 < 16) G2_ISSUE((k + 2) * 32, (k + 2) % 3);

        uint32_t ab = sb + (k % 3) * 10240;
        uint32_t bb = sb + 30720 + (k % 3) * 10240;

        uint32_t bg[4][4];
        #pragma unroll
        for (int g = 0; g < 4; g++) {
            int r = wn * 32 + g * 8 + (lane & 7);
            int cb = (lane >> 3) << 3;
            ldsm4(bg[g][0], bg[g][1], bg[g][2], bg[g][3], bb + (uint32_t)(r * 40 + cb) * 2);
        }
        #pragma unroll
        for (int kk = 0; kk < 2; kk++) {
            uint32_t aa[4][4];
            #pragma unroll
            for (int mf = 0; mf < 4; mf++) {
                int r = wm * 64 + mf * 16 + (lane & 15);
                int cb = kk * 16 + ((lane >> 4) << 3);
                ldsm4(aa[mf][0], aa[mf][1], aa[mf][2], aa[mf][3], ab + (uint32_t)(r * 40 + cb) * 2);
            }
            #pragma unroll
            for (int mf = 0; mf < 4; mf++)
                #pragma unroll
                for (int g = 0; g < 4; g++)
                    mma_bf16(c[mf][g], aa[mf][0], aa[mf][1], aa[mf][2], aa[mf][3],
                             bg[g][kk * 2], bg[g][kk * 2 + 1]);
        }
    }

    const float* bias = bq;
    if (QKV) {
        int which = n0 >> 9;
        bias = (which == 0) ? bq : (which == 1) ? bk : bv;
    }
    int nloc = QKV ? (n0 & 511) : n0;
    #pragma unroll
    for (int mf = 0; mf < 4; mf++) {
        int r0 = m0 + wm * 64 + mf * 16 + (lane >> 2);
        #pragma unroll
        for (int g = 0; g < 4; g++) {
            int cl = nloc + wn * 32 + g * 8 + 2 * (lane & 3);
            float b0v = bias[cl], b1v = bias[cl + 1];
            float v00 = c[mf][g][0] + b0v, v01 = c[mf][g][1] + b1v;
            float v10 = c[mf][g][2] + b0v, v11 = c[mf][g][3] + b1v;
            if (QKV) {
                __nv_bfloat16* C = (__nv_bfloat16*)Cout;
                int col = n0 + wn * 32 + g * 8 + 2 * (lane & 3);
                *reinterpret_cast<uint32_t*>(C + (size_t)r0 * QKVLD + col) = packh(v00, v01);
                *reinterpret_cast<uint32_t*>(C + (size_t)(r0 + 8) * QKVLD + col) = packh(v10, v11);
            } else {
                float* C = (float*)Cout;
                size_t off0 = (size_t)r0 * HDIM + cl;
                size_t off1 = (size_t)(r0 + 8) * HDIM + cl;
                float2 ra = *reinterpret_cast<const float2*>(&res[off0]);
                float2 rb = *reinterpret_cast<const float2*>(&res[off1]);
                *reinterpret_cast<float2*>(C + off0) = make_float2(v00 + ra.x, v01 + ra.y);
                *reinterpret_cast<float2*>(C + off1) = make_float2(v10 + rb.x, v11 + rb.y);
            }
        }
    }
}

// ---------------- attention: split-KV NSPLIT=2, l on fma pipe, batch-offset ----------------
#define A_QS 0
#define A_KS 16384
#define A_VS 32768
#define A_MK 49152
#define ATT_SMEM 51200

__global__ __launch_bounds__(128, 4) void att_mma_kernel(const __nv_bfloat16* __restrict__ QKV,
                                                         const float* __restrict__ mask,
                                                         uint32_t* __restrict__ Opart,
                                                         float* __restrict__ Lpart,
                                                         int b0) {
    extern __shared__ __align__(16) char asm_[];
    uint32_t sb = smem_u32(asm_);
    uint32_t* mskh2 = reinterpret_cast<uint32_t*>(asm_ + A_MK);

    int t = threadIdx.x, wid = t >> 5, lane = t & 31;
    int q0 = blockIdx.x * 128;
    int b = b0 + (blockIdx.y >> 3), h = blockIdx.y & 7;
    int split = blockIdx.z;
    int kt0 = split * KV_TILES_PER_SPLIT;
    int ktend = kt0 + KV_TILES_PER_SPLIT;

    const __nv_bfloat16* qg = QKV + (size_t)b * S_LEN * QKVLD + h * DHEAD;
    const __nv_bfloat16* kg = QKV + (size_t)b * S_LEN * QKVLD + 512 + h * DHEAD;
    const __nv_bfloat16* vg = QKV + (size_t)b * S_LEN * QKVLD + 1024 + h * DHEAD;

    #pragma unroll
    for (int e = 0; e < 8; e++) {
        int idx = t + e * 128;
        int r = idx >> 3, c8 = idx & 7;
        CP16(sb + A_QS + (uint32_t)(r * 128 + ((c8 ^ (r & 7)) << 4)),
             qg + (size_t)(q0 + r) * QKVLD + c8 * 8);
    }
    #pragma unroll
    for (int e = 0; e < 4; e++) {
        int idx = t + e * 128;
        int r = idx >> 3, c8 = idx & 7;
        uint32_t off = (uint32_t)(r * 128 + ((c8 ^ (r & 7)) << 4));
        CP16(sb + A_KS + off, kg + (size_t)(kt0 * 64 + r) * QKVLD + c8 * 8);
        CP16(sb + A_VS + off, vg + (size_t)(kt0 * 64 + r) * QKVLD + c8 * 8);
    }
    CP_COMMIT();
    #pragma unroll
    for (int e = 0; e < 4; e++) {
        int i = t + e * 128;
        float2 mv = reinterpret_cast<const float2*>(mask + (size_t)b * S_LEN)[split * 512 + i];
        mskh2[i] = packh(mv.x * LOG2E, mv.y * LOG2E);
    }
    CP_WAIT0();
    __syncthreads();

    uint32_t qa[2][4][4];
    #pragma unroll
    for (int mf = 0; mf < 2; mf++) {
        int r = wid * 32 + mf * 16 + (lane & 15);
        #pragma unroll
        for (int kk = 0; kk < 4; kk++) {
            int chunk = kk * 2 + (lane >> 4);
            ldsm4(qa[mf][kk][0], qa[mf][kk][1], qa[mf][kk][2], qa[mf][kk][3],
                  sb + A_QS + (uint32_t)(r * 128 + ((chunk ^ (lane & 7)) << 4)));
        }
    }

    uint32_t o[2][8][2] = {};
    float lacc[2][2] = {};
    const uint32_t sc2 = packh(0.125f * LOG2E, 0.125f * LOG2E);

    for (int kt = kt0; kt < ktend; kt++) {
        if (kt + 1 < ktend) {
            int kb1 = (kt + 1) * 64;
            uint32_t s1off = (uint32_t)((kt + 1) & 1) * 8192;
            #pragma unroll
            for (int e = 0; e < 4; e++) {
                int idx = t + e * 128;
                int r = idx >> 3, c8 = idx & 7;
                uint32_t off = s1off + (uint32_t)(r * 128 + ((c8 ^ (r & 7)) << 4));
                CP16(sb + A_KS + off, kg + (size_t)(kb1 + r) * QKVLD + c8 * 8);
                CP16(sb + A_VS + off, vg + (size_t)(kb1 + r) * QKVLD + c8 * 8);
            }
            CP_COMMIT();
        }

        uint32_t ks_b = sb + A_KS + (uint32_t)(kt & 1) * 8192;
        uint32_t vs_b = sb + A_VS + (uint32_t)(kt & 1) * 8192;
        int kbl = (kt - kt0) * 64;

        uint32_t s[2][8][2] = {};
        #pragma unroll
        for (int nn = 0; nn < 8; nn++) {
            int r = nn * 8 + (lane & 7);
            int c0 = ((lane >> 3) ^ (lane & 7)) << 4;
            int c1 = ((4 + (lane >> 3)) ^ (lane & 7)) << 4;
            uint32_t b0r, b1r, b2r, b3r, b4r, b5r, b6r, b7r;
            ldsm4(b0r, b1r, b2r, b3r, ks_b + (uint32_t)(r * 128 + c0));
            ldsm4(b4r, b5r, b6r, b7r, ks_b + (uint32_t)(r * 128 + c1));
            #pragma unroll
            for (int mf = 0; mf < 2; mf++) {
                mma_f16h(s[mf][nn], qa[mf][0][0], qa[mf][0][1], qa[mf][0][2], qa[mf][0][3], b0r, b1r);
                mma_f16h(s[mf][nn], qa[mf][1][0], qa[mf][1][1], qa[mf][1][2], qa[mf][1][3], b2r, b3r);
                mma_f16h(s[mf][nn], qa[mf][2][0], qa[mf][2][1], qa[mf][2][2], qa[mf][2][3], b4r, b5r);
                mma_f16h(s[mf][nn], qa[mf][3][0], qa[mf][3][1], qa[mf][3][2], qa[mf][3][3], b6r, b7r);
            }
        }

        #pragma unroll
        for (int mf = 0; mf < 2; mf++) {
            uint32_t lh0 = 0u, lh1 = 0u;
            #pragma unroll
            for (int nn = 0; nn < 8; nn++) {
                uint32_t mk = mskh2[(kbl >> 1) + nn * 4 + (lane & 3)];
                s[mf][nn][0] = ex2h2(hfma2(s[mf][nn][0], sc2, mk));
                s[mf][nn][1] = ex2h2(hfma2(s[mf][nn][1], sc2, mk));
                lh0 = hadd2u(lh0, s[mf][nn][0]);
                lh1 = hadd2u(lh1, s[mf][nn][1]);
            }
            float2 f0 = __half22float2(*reinterpret_cast<__half2*>(&lh0));
            float2 f1 = __half22float2(*reinterpret_cast<__half2*>(&lh1));
            lacc[mf][0] += f0.x + f0.y;
            lacc[mf][1] += f1.x + f1.y;
        }

        #pragma unroll
        for (int nn = 0; nn < 8; nn++) {
            uint32_t v0, v1, v2, v3, u0, u1, u2, u3;
            int ch = (nn ^ (lane & 7)) << 4;
            ldsm4t(v0, v1, v2, v3, vs_b + (uint32_t)(lane * 128 + ch));
            ldsm4t(u0, u1, u2, u3, vs_b + (uint32_t)((32 + lane) * 128 + ch));
            #pragma unroll
            for (int mf = 0; mf < 2; mf++) {
                mma_f16h(o[mf][nn], s[mf][0][0], s[mf][0][1], s[mf][1][0], s[mf][1][1], v0, v1);
                mma_f16h(o[mf][nn], s[mf][2][0], s[mf][2][1], s[mf][3][0], s[mf][3][1], v2, v3);
                mma_f16h(o[mf][nn], s[mf][4][0], s[mf][4][1], s[mf][5][0], s[mf][5][1], u0, u1);
                mma_f16h(o[mf][nn], s[mf][6][0], s[mf][6][1], s[mf][7][0], s[mf][7][1], u2, u3);
            }
        }

        if (kt + 1 < ktend) {
            CP_WAIT0();
            __syncthreads();
        }
    }

    #pragma unroll
    for (int mf = 0; mf < 2; mf++)
        #pragma unroll
        for (int i = 0; i < 2; i++) {
            lacc[mf][i] += __shfl_xor_sync(0xffffffffu, lacc[mf][i], 1);
            lacc[mf][i] += __shfl_xor_sync(0xffffffffu, lacc[mf][i], 2);
        }

    int rbase = b * S_LEN + q0 + wid * 32 + (lane >> 2);
    uint32_t* op = Opart + (size_t)split * ROWS * (HDIM / 2);
    #pragma unroll
    for (int nn = 0; nn < 8; nn++) {
        int colh = (h * DHEAD + nn * 8 + 2 * (lane & 3)) >> 1;
        #pragma unroll
        for (int mf = 0; mf < 2; mf++) {
            op[(size_t)(rbase + mf * 16) * (HDIM / 2) + colh] = o[mf][nn][0];
            op[(size_t)(rbase + mf * 16 + 8) * (HDIM / 2) + colh] = o[mf][nn][1];
        }
    }
    if ((lane & 3) == 0) {
        float* lp = Lpart + (size_t)split * ROWS * NHEADS;
        #pragma unroll
        for (int mf = 0; mf < 2; mf++) {
            lp[(size_t)(rbase + mf * 16) * NHEADS + h] = lacc[mf][0];
            lp[(size_t)(rbase + mf * 16 + 8) * NHEADS + h] = lacc[mf][1];
        }
    }
}

// ---------------- combine v2 (round-15), row-offset ----------------
__global__ __launch_bounds__(256) void att_combine_kernel(const uint32_t* __restrict__ Opart,
                                                          const float* __restrict__ Lpart,
                                                          __nv_bfloat16* __restrict__ ctx,
                                                          int row0) {
    int r  = row0 + blockIdx.x * 4 + (threadIdx.x >> 6);
    int tc = threadIdx.x & 63;
    int c8 = tc * 8;
    int h  = c8 >> 6;

    uint4 u0 = *reinterpret_cast<const uint4*>(Opart + (size_t)r * (HDIM / 2) + (c8 >> 1));
    uint4 u1 = *reinterpret_cast<const uint4*>(
        Opart + ((size_t)ROWS + r) * (HDIM / 2) + (c8 >> 1));
    float l0 = Lpart[(size_t)r * NHEADS + h];
    float l1 = Lpart[((size_t)ROWS + r) * NHEADS + h];
    float inv = 1.0f / (l0 + l1);

    const uint32_t* a = reinterpret_cast<const uint32_t*>(&u0);
    const uint32_t* bpa = reinterpret_cast<const uint32_t*>(&u1);
    uint2 ov[2];
    uint32_t* ovp = reinterpret_cast<uint32_t*>(ov);
    #pragma unroll
    for (int i = 0; i < 4; i++) {
        float2 f0 = __half22float2(*reinterpret_cast<const __half2*>(&a[i]));
        float2 f1 = __half22float2(*reinterpret_cast<const __half2*>(&bpa[i]));
        ovp[i] = packbf((f0.x + f1.x) * inv, (f0.y + f1.y) * inv);
    }
    *reinterpret_cast<uint4*>(ctx + (size_t)r * HDIM + c8) =
        *reinterpret_cast<uint4*>(ov);
}

// ---------------- launcher: two-stream batch-split overlap ----------------
extern "C" void kernel_launch(void* const* d_in, const int* in_sizes, int n_in,
                              void* d_out, int out_size) {
    const float* hidden = (const float*)d_in[0];
    const float* amask  = (const float*)d_in[1];
    const float* ln1_g  = (const float*)d_in[2];
    const float* ln1_b  = (const float*)d_in[3];
    const float* wq     = (const float*)d_in[4];
    const float* bq     = (const float*)d_in[5];
    const float* wk     = (const float*)d_in[6];
    const float* bk     = (const float*)d_in[7];
    const float* wv     = (const float*)d_in[8];
    const float* bv     = (const float*)d_in[9];
    const float* wo     = (const float*)d_in[10];
    const float* bo     = (const float*)d_in[11];
    const float* ln2_g  = (const float*)d_in[12];
    const float* ln2_b  = (const float*)d_in[13];
    float* out = (float*)d_out;

    float* scrf = nullptr;
    __nv_bfloat16* scrb = nullptr;
    uint32_t* opart = nullptr;
    float* lpart = nullptr;
    cudaGetSymbolAddress((void**)&scrf, g_scratch_f);
    cudaGetSymbolAddress((void**)&scrb, g_scratch_b);
    cudaGetSymbolAddress((void**)&opart, g_opart);
    cudaGetSymbolAddress((void**)&lpart, g_lpart);
    const size_t SZ = (size_t)ROWS * HDIM;
    const size_t WSZ = (size_t)HDIM * HDIM;
    float* g_h = scrf;
    float* g_t = scrf + SZ;
    __nv_bfloat16* g_hb   = scrb;
    __nv_bfloat16* g_qkv  = scrb + SZ;          // [ROWS][1536], fp16 bits
    __nv_bfloat16* g_ctxb = scrb + 4 * SZ;
    __nv_bfloat16* g_wb   = scrb + 5 * SZ;      // wq|wk|wv|wo

    static cudaStream_t s2 = nullptr;
    static cudaEvent_t evFork = nullptr, evJoin = nullptr;
    static bool attr_done = false;
    if (!attr_done) {
        cudaFuncSetAttribute(gemm2_kernel<true>,  cudaFuncAttributeMaxDynamicSharedMemorySize, G2_SMEM);
        cudaFuncSetAttribute(gemm2_kernel<false>, cudaFuncAttributeMaxDynamicSharedMemorySize, G2_SMEM);
        cudaFuncSetAttribute(att_mma_kernel,      cudaFuncAttributeMaxDynamicSharedMemorySize, ATT_SMEM);
        cudaStreamCreateWithFlags(&s2, cudaStreamNonBlocking);
        cudaEventCreateWithFlags(&evFork, cudaEventDisableTiming);
        cudaEventCreateWithFlags(&evJoin, cudaEventDisableTiming);
        attr_done = true;
    }

    // 1) fused LN1 + weight conversion (all rows) on the main stream
    ln_conv_kernel<<<ROWS + 2048, 128>>>(hidden, ln1_g, ln1_b, g_h, g_hb,
                                         wq, wk, wv, wo, g_wb);
    cudaEventRecord(evFork, 0);
    cudaStreamWaitEvent(s2, evFork, 0);

    // 2) per-batch-half chains on two streams
    dim3 qkv_grid(3 * HDIM / 128, HALF_ROWS / 128);        // (12, 32)
    dim3 att_grid(S_LEN / 128, 2 * NHEADS, NSPLIT);        // (16, 16, 2)
    dim3 wo_grid(HDIM / 128, HALF_ROWS / 128);             // (4, 32)

    for (int half = 0; half < 2; half++) {
        cudaStream_t st = (half == 0) ? (cudaStream_t)0 : s2;
        int row0 = half * HALF_ROWS;
        int b0 = half * 2;
        gemm2_kernel<true><<<qkv_grid, 256, G2_SMEM, st>>>(g_hb, g_wb, bq, bk, bv,
                                                           nullptr, g_qkv, row0);
        att_mma_kernel<<<att_grid, 128, ATT_SMEM, st>>>(g_qkv, amask, opart, lpart, b0);
        att_combine_kernel<<<HALF_ROWS / 4, 256, 0, st>>>(opart, lpart, g_ctxb, row0);
        gemm2_kernel<false><<<wo_grid, 256, G2_SMEM, st>>>(g_ctxb, g_wb + 3 * WSZ, bo,
                                                           nullptr, nullptr, g_h, g_t, row0);
        ln_kernel<<<HALF_ROWS, 128, 0, st>>>(g_t, ln2_g, ln2_b, out, row0);
    }

    cudaEventRecord(evJoin, s2);
    cudaStreamWaitEvent(0, evJoin, 0);
}